// round 15
// baseline (speedup 1.0000x reference)
#include <cuda_runtime.h>
#include <cuda_fp16.h>

#define NN 50000
#define EE 800000
#define DM 128
#define RD 32
#define LN_EPS 1e-5f
#define NT2 ((NN + 255) / 256)   // 196 tiles of 256 nodes

// ---------------- scratch ------------------------------------------------------
__device__ __half g_hA[NN * DM];
__device__ __half g_hB[NN * DM];
__device__ __half g_aggH[NN * DM];
__device__ __half g_aggR[NN * RD];
__device__ float  g_part[NN * DM];   // fp32 partial: h @ Wself
__device__ float  g_inv[NN];
__device__ int    g_deg[NN];
__device__ int    g_off[NN + 1];
__device__ int    g_cur[NN];
__device__ int2   g_csr[EE];

// ---------------- CSR build ----------------------------------------------------
__global__ void k_deg(const int* __restrict__ dst) {
    int i = blockIdx.x * blockDim.x + threadIdx.x;
    if (i < EE) atomicAdd(&g_deg[dst[i]], 1);
}

__global__ __launch_bounds__(1024) void k_scan() {
    __shared__ int wsum[32];
    __shared__ int sh_carry;
    int t = threadIdx.x, lane = t & 31, w = t >> 5;
    if (t == 0) sh_carry = 0;
    __syncthreads();

    for (int base = 0; base < NN; base += 1024) {
        int idx = base + t;
        int d = (idx < NN) ? g_deg[idx] : 0;
        int carry = sh_carry;

        int incl = d;
        #pragma unroll
        for (int o = 1; o < 32; o <<= 1) {
            int u = __shfl_up_sync(0xffffffffu, incl, o);
            if (lane >= o) incl += u;
        }
        if (lane == 31) wsum[w] = incl;
        __syncthreads();
        if (w == 0) {
            int u = wsum[lane];
            #pragma unroll
            for (int o = 1; o < 32; o <<= 1) {
                int uu = __shfl_up_sync(0xffffffffu, u, o);
                if (lane >= o) u += uu;
            }
            wsum[lane] = u;
        }
        __syncthreads();

        int excl = carry + (w > 0 ? wsum[w - 1] : 0) + incl - d;
        if (idx < NN) {
            g_off[idx] = excl;
            g_cur[idx] = excl;
            g_inv[idx] = d > 0 ? (1.f / (float)d) : 0.f;
        }
        int total = wsum[31];
        __syncthreads();
        if (t == 0) sh_carry = carry + total;
        __syncthreads();
    }
    if (t == 0) g_off[NN] = EE;
}

__global__ void k_scatter(const int* __restrict__ src, const int* __restrict__ dst,
                          const int* __restrict__ erel) {
    int i = blockIdx.x * blockDim.x + threadIdx.x;
    if (i < EE) {
        int d = dst[i];
        int pos = atomicAdd(&g_cur[d], 1);
        g_csr[pos] = make_int2(src[i], erel[i]);
    }
}

// ---------------- gather (fp16 h) ------------------------------------------------
__device__ __forceinline__ void acc_h4(float4& a, uint2 hw) {
    float2 lo = __half22float2(*reinterpret_cast<__half2*>(&hw.x));
    float2 hi = __half22float2(*reinterpret_cast<__half2*>(&hw.y));
    a.x += lo.x; a.y += lo.y; a.z += hi.x; a.w += hi.y;
}

__global__ __launch_bounds__(256) void k_gather(
    const __half* __restrict__ hin, const float* __restrict__ rel)
{
    __shared__ int2 stage[8][32];
    int w = threadIdx.x >> 5, lane = threadIdx.x & 31;
    int v = blockIdx.x * 8 + w;
    if (v >= NN) return;
    int2* st = stage[w];
    const uint2* hb = (const uint2*)hin;

    int e = g_off[v], end = g_off[v + 1];
    float4 a0 = make_float4(0.f, 0.f, 0.f, 0.f), a1 = a0, a2 = a0, a3 = a0;
    float r0s = 0.f, r1s = 0.f, r2s = 0.f, r3s = 0.f;

    while (e < end) {
        int n = min(32, end - e);
        if (lane < n) st[lane] = g_csr[e + lane];
        __syncwarp();
        int j = 0;
        for (; j + 4 <= n; j += 4) {
            int2 p0 = st[j], p1 = st[j + 1], p2 = st[j + 2], p3 = st[j + 3];
            uint2 h0 = hb[(size_t)p0.x * 32 + lane];
            uint2 h1 = hb[(size_t)p1.x * 32 + lane];
            uint2 h2 = hb[(size_t)p2.x * 32 + lane];
            uint2 h3 = hb[(size_t)p3.x * 32 + lane];
            float q0 = rel[p0.y * RD + lane];
            float q1 = rel[p1.y * RD + lane];
            float q2 = rel[p2.y * RD + lane];
            float q3 = rel[p3.y * RD + lane];
            acc_h4(a0, h0); acc_h4(a1, h1); acc_h4(a2, h2); acc_h4(a3, h3);
            r0s += q0; r1s += q1; r2s += q2; r3s += q3;
        }
        for (; j < n; j++) {
            int2 p0 = st[j];
            uint2 h0 = hb[(size_t)p0.x * 32 + lane];
            acc_h4(a0, h0);
            r0s += rel[p0.y * RD + lane];
        }
        e += n;
        __syncwarp();
    }

    float iv = g_inv[v];
    float4 acc;
    acc.x = (a0.x + a1.x + a2.x + a3.x) * iv;
    acc.y = (a0.y + a1.y + a2.y + a3.y) * iv;
    acc.z = (a0.z + a1.z + a2.z + a3.z) * iv;
    acc.w = (a0.w + a1.w + a2.w + a3.w) * iv;
    uint2 outw;
    __half2 lo = __floats2half2_rn(acc.x, acc.y);
    __half2 hi = __floats2half2_rn(acc.z, acc.w);
    outw.x = *reinterpret_cast<unsigned*>(&lo);
    outw.y = *reinterpret_cast<unsigned*>(&hi);
    ((uint2*)g_aggH)[(size_t)v * 32 + lane] = outw;
    g_aggR[v * RD + lane] = __float2half((r0s + r1s + r2s + r3s) * iv);
}

// ---------------- fp16 mma machinery ---------------------------------------------
extern __shared__ float smdyn[];

__device__ __forceinline__ unsigned ldh2(const float* p) {
    float2 f = *(const float2*)p;
    __half2 h = __float22half2_rn(f);
    return *(unsigned*)&h;
}
__device__ __forceinline__ unsigned packh2(float a, float b) {
    __half2 h = __floats2half2_rn(a, b);
    return *(unsigned*)&h;
}

#define MMA_H(CI, A0, A1, A2, A3, B0, B1)                                       \
    asm("mma.sync.aligned.m16n8k16.row.col.f32.f16.f16.f32 "                    \
        "{%0,%1,%2,%3},{%4,%5,%6,%7},{%8,%9},{%0,%1,%2,%3};"                    \
        : "+f"(c[(CI)]), "+f"(c[(CI)+1]), "+f"(c[(CI)+2]), "+f"(c[(CI)+3])      \
        : "r"(A0), "r"(A1), "r"(A2), "r"(A3), "r"(B0), "r"(B1));

#define MMA_ROW16H(BP)                                                          \
    _Pragma("unroll")                                                           \
    for (int nt = 0; nt < 16; nt++) {                                           \
        uint2 b = (BP)[nt * 32];                                                \
        MMA_H(nt * 4, a0, a1, a2, a3, b.x, b.y)                                 \
    }

// ---------------- input projection ------------------------------------------------
__global__ __launch_bounds__(512) void k_input(
    const float* __restrict__ x, const int* __restrict__ label,
    const float* __restrict__ lemb, const float* __restrict__ W,
    const float* __restrict__ b, __half* __restrict__ hout)
{
    float* bs = smdyn;
    uint2* Bp = (uint2*)(bs + DM);           // 10*512 uint2

    int tid = threadIdx.x;
    for (int idx = tid; idx < 10 * 512; idx += 512) {
        int kk = idx >> 9, r = idx & 511;
        int nt = r >> 5, ln = r & 31;
        int n = nt * 8 + (ln >> 2);
        int kb = kk * 16 + (ln & 3) * 2;
        unsigned r0 = packh2(W[kb * DM + n],       W[(kb + 1) * DM + n]);
        unsigned r1 = packh2(W[(kb + 8) * DM + n], W[(kb + 9) * DM + n]);
        Bp[idx] = make_uint2(r0, r1);
    }
    for (int i = tid; i < DM; i += 512) bs[i] = b[i];
    __syncthreads();

    int w = tid >> 5, lane = tid & 31, q = lane & 3, g = lane >> 2;
    const uint2* bpl = Bp + lane;

    for (int tb = blockIdx.x; tb < NT2; tb += gridDim.x) {
        int v0w = tb * 256 + w * 16;
        if (v0w >= NN) continue;
        int va = min(v0w + g, NN - 1);
        int vb = min(v0w + g + 8, NN - 1);
        int la = __ldg(&label[va]);
        int lb = __ldg(&label[vb]);

        float c[64];
        #pragma unroll
        for (int i = 0; i < 64; i++) c[i] = 0.f;

        #pragma unroll
        for (int kk = 0; kk < 8; kk++) {
            int kb = kk * 16 + q * 2;
            unsigned a0 = ldh2(x + (size_t)va * DM + kb);
            unsigned a1 = ldh2(x + (size_t)vb * DM + kb);
            unsigned a2 = ldh2(x + (size_t)va * DM + kb + 8);
            unsigned a3 = ldh2(x + (size_t)vb * DM + kb + 8);
            const uint2* bp = bpl + kk * 512;
            MMA_ROW16H(bp)
        }
        #pragma unroll
        for (int kk = 8; kk < 10; kk++) {
            int kb = kk * 16 + q * 2 - 128;
            unsigned a0 = ldh2(lemb + (size_t)la * RD + kb);
            unsigned a1 = ldh2(lemb + (size_t)lb * RD + kb);
            unsigned a2 = ldh2(lemb + (size_t)la * RD + kb + 8);
            unsigned a3 = ldh2(lemb + (size_t)lb * RD + kb + 8);
            const uint2* bp = bpl + kk * 512;
            MMA_ROW16H(bp)
        }

        int ra = v0w + g, rb = v0w + g + 8;
        #pragma unroll
        for (int nt = 0; nt < 16; nt++) {
            float2 bv = *(float2*)(bs + nt * 8 + 2 * q);
            if (ra < NN) {
                *(unsigned*)(hout + (size_t)ra * DM + nt * 8 + 2 * q) =
                    packh2(fmaxf(c[nt*4+0] + bv.x, 0.f), fmaxf(c[nt*4+1] + bv.y, 0.f));
            }
            if (rb < NN) {
                *(unsigned*)(hout + (size_t)rb * DM + nt * 8 + 2 * q) =
                    packh2(fmaxf(c[nt*4+2] + bv.x, 0.f), fmaxf(c[nt*4+3] + bv.y, 0.f));
            }
        }
    }
}

// ---------------- nodeS: partial = hin @ Wself (runs concurrent with gather) -----
__global__ __launch_bounds__(512) void k_nodeS(
    const __half* __restrict__ hin, const float* __restrict__ Wself)
{
    uint2* Bp = (uint2*)smdyn;               // 8*512 uint2
    int tid = threadIdx.x;
    for (int idx = tid; idx < 8 * 512; idx += 512) {
        int kk = idx >> 9, r = idx & 511;
        int nt = r >> 5, ln = r & 31;
        int n = nt * 8 + (ln >> 2);
        int kb = kk * 16 + (ln & 3) * 2;
        Bp[idx] = make_uint2(packh2(Wself[kb * DM + n],       Wself[(kb + 1) * DM + n]),
                             packh2(Wself[(kb + 8) * DM + n], Wself[(kb + 9) * DM + n]));
    }
    __syncthreads();

    int w = tid >> 5, lane = tid & 31, q = lane & 3, g = lane >> 2;
    const uint2* bpl = Bp + lane;

    for (int tb = blockIdx.x; tb < NT2; tb += gridDim.x) {
        int v0w = tb * 256 + w * 16;
        if (v0w >= NN) continue;
        int va = min(v0w + g, NN - 1);
        int vb = min(v0w + g + 8, NN - 1);

        float c[64];
        #pragma unroll
        for (int i = 0; i < 64; i++) c[i] = 0.f;

        #pragma unroll
        for (int kk = 0; kk < 8; kk++) {
            int kb = kk * 16 + q * 2;
            unsigned a0 = *(const unsigned*)(hin + (size_t)va * DM + kb);
            unsigned a1 = *(const unsigned*)(hin + (size_t)vb * DM + kb);
            unsigned a2 = *(const unsigned*)(hin + (size_t)va * DM + kb + 8);
            unsigned a3 = *(const unsigned*)(hin + (size_t)vb * DM + kb + 8);
            const uint2* bp = bpl + kk * 512;
            MMA_ROW16H(bp)
        }

        int ra = v0w + g, rb = v0w + g + 8;
        #pragma unroll
        for (int nt = 0; nt < 16; nt++) {
            if (ra < NN)
                *(float2*)(g_part + (size_t)ra * DM + nt * 8 + 2 * q) =
                    make_float2(c[nt*4+0], c[nt*4+1]);
            if (rb < NN)
                *(float2*)(g_part + (size_t)rb * DM + nt * 8 + 2 * q) =
                    make_float2(c[nt*4+2], c[nt*4+3]);
        }
    }
}

// ---------------- nodeR: part + aggH@Wn + aggR@Wr + bias + relu + LN --------------
__global__ __launch_bounds__(512) void k_nodeR(
    const float* __restrict__ Wn, const float* __restrict__ Wr,
    const float* __restrict__ bias, const float* __restrict__ lng,
    const float* __restrict__ lnb,
    __half* __restrict__ hout_h, float* __restrict__ hout_f)
{
    float* bs  = smdyn;                      // 128
    float* gs  = bs + DM;                    // 128
    float* lbs = gs + DM;                    // 128
    uint2* Bp  = (uint2*)(lbs + DM);         // 10*512 uint2

    int tid = threadIdx.x;
    for (int idx = tid; idx < 10 * 512; idx += 512) {
        int kk = idx >> 9, r = idx & 511;
        int nt = r >> 5, ln = r & 31;
        int n = nt * 8 + (ln >> 2);
        int kb = kk * 16 + (ln & 3) * 2;
        float w00, w01, w10, w11;
        if (kb < 128) {
            w00 = Wn[kb * DM + n];       w01 = Wn[(kb + 1) * DM + n];
            w10 = Wn[(kb + 8) * DM + n]; w11 = Wn[(kb + 9) * DM + n];
        } else {
            int k2 = kb - 128;
            w00 = Wr[k2 * DM + n];       w01 = Wr[(k2 + 1) * DM + n];
            w10 = Wr[(k2 + 8) * DM + n]; w11 = Wr[(k2 + 9) * DM + n];
        }
        Bp[idx] = make_uint2(packh2(w00, w01), packh2(w10, w11));
    }
    for (int i = tid; i < DM; i += 512) {
        bs[i] = bias[i]; gs[i] = lng[i]; lbs[i] = lnb[i];
    }
    __syncthreads();

    int w = tid >> 5, lane = tid & 31, q = lane & 3, g = lane >> 2;
    const uint2* bpl = Bp + lane;

    for (int tb = blockIdx.x; tb < NT2; tb += gridDim.x) {
        int v0w = tb * 256 + w * 16;
        if (v0w >= NN) continue;
        int va = min(v0w + g, NN - 1);
        int vb = min(v0w + g + 8, NN - 1);

        // init accumulators from fp32 partial (self GEMM)
        float c[64];
        #pragma unroll
        for (int nt = 0; nt < 16; nt++) {
            float2 pa = *(const float2*)(g_part + (size_t)va * DM + nt * 8 + 2 * q);
            float2 pb = *(const float2*)(g_part + (size_t)vb * DM + nt * 8 + 2 * q);
            c[nt*4+0] = pa.x; c[nt*4+1] = pa.y;
            c[nt*4+2] = pb.x; c[nt*4+3] = pb.y;
        }

        #pragma unroll
        for (int kk = 0; kk < 8; kk++) {
            int kb = kk * 16 + q * 2;
            unsigned a0 = *(const unsigned*)(g_aggH + (size_t)va * DM + kb);
            unsigned a1 = *(const unsigned*)(g_aggH + (size_t)vb * DM + kb);
            unsigned a2 = *(const unsigned*)(g_aggH + (size_t)va * DM + kb + 8);
            unsigned a3 = *(const unsigned*)(g_aggH + (size_t)vb * DM + kb + 8);
            const uint2* bp = bpl + kk * 512;
            MMA_ROW16H(bp)
        }
        #pragma unroll
        for (int kk = 8; kk < 10; kk++) {
            int kb = (kk - 8) * 16 + q * 2;
            unsigned a0 = *(const unsigned*)(g_aggR + (size_t)va * RD + kb);
            unsigned a1 = *(const unsigned*)(g_aggR + (size_t)vb * RD + kb);
            unsigned a2 = *(const unsigned*)(g_aggR + (size_t)va * RD + kb + 8);
            unsigned a3 = *(const unsigned*)(g_aggR + (size_t)vb * RD + kb + 8);
            const uint2* bp = bpl + kk * 512;
            MMA_ROW16H(bp)
        }

        float s1a = 0.f, s2a = 0.f, s1b = 0.f, s2b = 0.f;
        #pragma unroll
        for (int nt = 0; nt < 16; nt++) {
            float2 bv = *(float2*)(bs + nt * 8 + 2 * q);
            float c0 = fmaxf(c[nt*4+0] + bv.x, 0.f);
            float c1 = fmaxf(c[nt*4+1] + bv.y, 0.f);
            float c2 = fmaxf(c[nt*4+2] + bv.x, 0.f);
            float c3 = fmaxf(c[nt*4+3] + bv.y, 0.f);
            c[nt*4+0] = c0; c[nt*4+1] = c1; c[nt*4+2] = c2; c[nt*4+3] = c3;
            s1a += c0 + c1; s2a += c0 * c0 + c1 * c1;
            s1b += c2 + c3; s2b += c2 * c2 + c3 * c3;
        }
        #pragma unroll
        for (int m = 1; m <= 2; m <<= 1) {
            s1a += __shfl_xor_sync(0xffffffffu, s1a, m);
            s2a += __shfl_xor_sync(0xffffffffu, s2a, m);
            s1b += __shfl_xor_sync(0xffffffffu, s1b, m);
            s2b += __shfl_xor_sync(0xffffffffu, s2b, m);
        }
        float mua = s1a * (1.f / 128.f);
        float rsa = rsqrtf(s2a * (1.f / 128.f) - mua * mua + LN_EPS);
        float mub = s1b * (1.f / 128.f);
        float rsb = rsqrtf(s2b * (1.f / 128.f) - mub * mub + LN_EPS);

        int ra = v0w + g, rb = v0w + g + 8;
        if (hout_f) {
            #pragma unroll
            for (int nt = 0; nt < 16; nt++) {
                float2 gv = *(float2*)(gs + nt * 8 + 2 * q);
                float2 lv = *(float2*)(lbs + nt * 8 + 2 * q);
                if (ra < NN) {
                    float2 o = make_float2((c[nt*4+0] - mua) * rsa * gv.x + lv.x,
                                           (c[nt*4+1] - mua) * rsa * gv.y + lv.y);
                    *(float2*)(hout_f + (size_t)ra * DM + nt * 8 + 2 * q) = o;
                }
                if (rb < NN) {
                    float2 o = make_float2((c[nt*4+2] - mub) * rsb * gv.x + lv.x,
                                           (c[nt*4+3] - mub) * rsb * gv.y + lv.y);
                    *(float2*)(hout_f + (size_t)rb * DM + nt * 8 + 2 * q) = o;
                }
            }
        } else {
            #pragma unroll
            for (int nt = 0; nt < 16; nt++) {
                float2 gv = *(float2*)(gs + nt * 8 + 2 * q);
                float2 lv = *(float2*)(lbs + nt * 8 + 2 * q);
                if (ra < NN) {
                    *(unsigned*)(hout_h + (size_t)ra * DM + nt * 8 + 2 * q) =
                        packh2((c[nt*4+0] - mua) * rsa * gv.x + lv.x,
                               (c[nt*4+1] - mua) * rsa * gv.y + lv.y);
                }
                if (rb < NN) {
                    *(unsigned*)(hout_h + (size_t)rb * DM + nt * 8 + 2 * q) =
                        packh2((c[nt*4+2] - mub) * rsb * gv.x + lv.x,
                               (c[nt*4+3] - mub) * rsb * gv.y + lv.y);
                }
            }
        }
    }
}

// ---------------- host launch ------------------------------------------------------
extern "C" void kernel_launch(void* const* d_in, const int* in_sizes, int n_in,
                              void* d_out, int out_size)
{
    const float* x      = (const float*)d_in[0];
    const int*   label  = (const int*)d_in[1];
    const int*   eidx   = (const int*)d_in[2];
    const int*   erel   = (const int*)d_in[3];
    const float* lemb   = (const float*)d_in[4];
    const float* Win    = (const float*)d_in[5];
    const float* bin    = (const float*)d_in[6];
    const float* relemb = (const float*)d_in[7];
    const float* Wn     = (const float*)d_in[8];
    const float* Wself  = (const float*)d_in[9];
    const float* bself  = (const float*)d_in[10];
    const float* Wr     = (const float*)d_in[11];
    const float* lng    = (const float*)d_in[12];
    const float* lnb    = (const float*)d_in[13];
    float* out = (float*)d_out;

    __half *p_hA, *p_hB;
    int *p_deg;
    cudaGetSymbolAddress((void**)&p_hA,  g_hA);
    cudaGetSymbolAddress((void**)&p_hB,  g_hB);
    cudaGetSymbolAddress((void**)&p_deg, g_deg);

    const int smemI = 512 + 10 * 512 * 8;          // 41472
    const int smemS = 8 * 512 * 8;                 // 32768
    const int smemR = 1536 + 10 * 512 * 8;         // 42496
    cudaFuncSetAttribute(k_input, cudaFuncAttributeMaxDynamicSharedMemorySize, smemI);
    cudaFuncSetAttribute(k_nodeS, cudaFuncAttributeMaxDynamicSharedMemorySize, smemS);
    cudaFuncSetAttribute(k_nodeR, cudaFuncAttributeMaxDynamicSharedMemorySize, smemR);

    cudaStream_t s2;
    cudaEvent_t evFork, evIn, evS0, evN0, evS1;
    cudaStreamCreateWithFlags(&s2, cudaStreamNonBlocking);
    cudaEventCreateWithFlags(&evFork, cudaEventDisableTiming);
    cudaEventCreateWithFlags(&evIn,   cudaEventDisableTiming);
    cudaEventCreateWithFlags(&evS0,   cudaEventDisableTiming);
    cudaEventCreateWithFlags(&evN0,   cudaEventDisableTiming);
    cudaEventCreateWithFlags(&evS1,   cudaEventDisableTiming);

    cudaEventRecord(evFork, 0);
    cudaStreamWaitEvent(s2, evFork, 0);

    // s2: input projection, then self-GEMM of layer 0 (needs only hA + Wself)
    k_input<<<148, 512, smemI, s2>>>(x, label, lemb, Win, bin, p_hA);
    cudaEventRecord(evIn, s2);
    k_nodeS<<<148, 512, smemS, s2>>>(p_hA, Wself + 0 * DM * DM);
    cudaEventRecord(evS0, s2);

    // s0: CSR build, then layer-0 gather (needs CSR + hA)
    cudaMemsetAsync(p_deg, 0, NN * sizeof(int));
    k_deg<<<(EE + 255) / 256, 256>>>(eidx + EE);
    k_scan<<<1, 1024>>>();
    k_scatter<<<(EE + 255) / 256, 256>>>(eidx, eidx + EE, erel);
    cudaStreamWaitEvent(0, evIn, 0);
    k_gather<<<(NN + 7) / 8, 256>>>(p_hA, relemb + 0 * 1024 * RD);

    // s0: layer-0 rest (needs gather + partial)
    cudaStreamWaitEvent(0, evS0, 0);
    k_nodeR<<<148, 512, smemR>>>(Wn + 0 * DM * DM, Wr + 0 * RD * DM,
                                 bself + 0 * DM, lng + 0 * DM, lnb + 0 * DM,
                                 p_hB, (float*)nullptr);
    cudaEventRecord(evN0, 0);

    // layer 1: s2 self-GEMM (after nodeR0: hB ready + g_part free) || s0 gather
    cudaStreamWaitEvent(s2, evN0, 0);
    k_nodeS<<<148, 512, smemS, s2>>>(p_hB, Wself + 1 * DM * DM);
    cudaEventRecord(evS1, s2);

    k_gather<<<(NN + 7) / 8, 256>>>(p_hB, relemb + 1 * 1024 * RD);
    cudaStreamWaitEvent(0, evS1, 0);
    k_nodeR<<<148, 512, smemR>>>(Wn + 1 * DM * DM, Wr + 1 * RD * DM,
                                 bself + 1 * DM, lng + 1 * DM, lnb + 1 * DM,
                                 (__half*)nullptr, out);

    cudaEventDestroy(evFork);
    cudaEventDestroy(evIn);
    cudaEventDestroy(evS0);
    cudaEventDestroy(evN0);
    cudaEventDestroy(evS1);
    cudaStreamDestroy(s2);
}

// round 16
// speedup vs baseline: 1.1180x; 1.1180x over previous
#include <cuda_runtime.h>
#include <cuda_fp16.h>

#define NN 50000
#define EE 800000
#define DM 128
#define RD 32
#define LN_EPS 1e-5f
#define NT2 ((NN + 255) / 256)   // 196 tiles of 256 nodes
#define SCAN_B ((NN + 1023) / 1024)   // 49 scan blocks

// ---------------- scratch ------------------------------------------------------
__device__ __half g_hA[NN * DM];
__device__ __half g_hB[NN * DM];
__device__ __half g_aggH[NN * DM];
__device__ __half g_aggR[NN * RD];
__device__ float  g_part[NN * DM];   // fp32 partial: h @ Wself
__device__ float  g_inv[NN];
__device__ int    g_deg[NN];
__device__ int    g_off[NN + 1];
__device__ int    g_cur[NN];
__device__ int    g_bsum[SCAN_B];
__device__ int2   g_csr[EE];

// ---------------- CSR build ----------------------------------------------------
__global__ void k_deg(const int* __restrict__ dst) {
    int i = blockIdx.x * blockDim.x + threadIdx.x;
    if (i < EE) atomicAdd(&g_deg[dst[i]], 1);
}

// phase A: per-block exclusive prefix (local) + block sums + inv_deg
__global__ __launch_bounds__(1024) void k_scanA() {
    __shared__ int wsum[32];
    int t = threadIdx.x, lane = t & 31, w = t >> 5;
    int idx = blockIdx.x * 1024 + t;
    int d = (idx < NN) ? g_deg[idx] : 0;

    int incl = d;
    #pragma unroll
    for (int o = 1; o < 32; o <<= 1) {
        int u = __shfl_up_sync(0xffffffffu, incl, o);
        if (lane >= o) incl += u;
    }
    if (lane == 31) wsum[w] = incl;
    __syncthreads();
    if (w == 0) {
        int u = wsum[lane];
        #pragma unroll
        for (int o = 1; o < 32; o <<= 1) {
            int uu = __shfl_up_sync(0xffffffffu, u, o);
            if (lane >= o) u += uu;
        }
        wsum[lane] = u;
    }
    __syncthreads();

    int excl = (w > 0 ? wsum[w - 1] : 0) + incl - d;
    if (idx < NN) {
        g_off[idx] = excl;      // local (block-relative) for now
        g_inv[idx] = d > 0 ? (1.f / (float)d) : 0.f;
    }
    if (t == 0) g_bsum[blockIdx.x] = wsum[31];
}

// phase B: exclusive scan of the SCAN_B block sums (one 64-thread block)
__global__ void k_scanB() {
    __shared__ int ws[2];
    int t = threadIdx.x, lane = t & 31, w = t >> 5;
    int v = (t < SCAN_B) ? g_bsum[t] : 0;
    int incl = v;
    #pragma unroll
    for (int o = 1; o < 32; o <<= 1) {
        int u = __shfl_up_sync(0xffffffffu, incl, o);
        if (lane >= o) incl += u;
    }
    if (lane == 31) ws[w] = incl;
    __syncthreads();
    int add = (w == 1) ? ws[0] : 0;
    if (t < SCAN_B) g_bsum[t] = incl - v + add;
}

// phase C: add block offsets, fill g_cur, cap sentinel
__global__ __launch_bounds__(1024) void k_scanC() {
    int idx = blockIdx.x * 1024 + threadIdx.x;
    if (idx < NN) {
        int o = g_off[idx] + g_bsum[blockIdx.x];
        g_off[idx] = o;
        g_cur[idx] = o;
    }
    if (blockIdx.x == 0 && threadIdx.x == 0) g_off[NN] = EE;
}

__global__ void k_scatter(const int* __restrict__ src, const int* __restrict__ dst,
                          const int* __restrict__ erel) {
    int i = blockIdx.x * blockDim.x + threadIdx.x;
    if (i < EE) {
        int d = dst[i];
        int pos = atomicAdd(&g_cur[d], 1);
        g_csr[pos] = make_int2(src[i], erel[i]);
    }
}

// ---------------- gather (fp16 h) ------------------------------------------------
__device__ __forceinline__ void acc_h4(float4& a, uint2 hw) {
    float2 lo = __half22float2(*reinterpret_cast<__half2*>(&hw.x));
    float2 hi = __half22float2(*reinterpret_cast<__half2*>(&hw.y));
    a.x += lo.x; a.y += lo.y; a.z += hi.x; a.w += hi.y;
}

__global__ __launch_bounds__(256) void k_gather(
    const __half* __restrict__ hin, const float* __restrict__ rel)
{
    __shared__ int2 stage[8][32];
    int w = threadIdx.x >> 5, lane = threadIdx.x & 31;
    int v = blockIdx.x * 8 + w;
    if (v >= NN) return;
    int2* st = stage[w];
    const uint2* hb = (const uint2*)hin;

    int e = g_off[v], end = g_off[v + 1];
    float4 a0 = make_float4(0.f, 0.f, 0.f, 0.f), a1 = a0, a2 = a0, a3 = a0;
    float r0s = 0.f, r1s = 0.f, r2s = 0.f, r3s = 0.f;

    while (e < end) {
        int n = min(32, end - e);
        if (lane < n) st[lane] = g_csr[e + lane];
        __syncwarp();
        int j = 0;
        for (; j + 4 <= n; j += 4) {
            int2 p0 = st[j], p1 = st[j + 1], p2 = st[j + 2], p3 = st[j + 3];
            uint2 h0 = hb[(size_t)p0.x * 32 + lane];
            uint2 h1 = hb[(size_t)p1.x * 32 + lane];
            uint2 h2 = hb[(size_t)p2.x * 32 + lane];
            uint2 h3 = hb[(size_t)p3.x * 32 + lane];
            float q0 = rel[p0.y * RD + lane];
            float q1 = rel[p1.y * RD + lane];
            float q2 = rel[p2.y * RD + lane];
            float q3 = rel[p3.y * RD + lane];
            acc_h4(a0, h0); acc_h4(a1, h1); acc_h4(a2, h2); acc_h4(a3, h3);
            r0s += q0; r1s += q1; r2s += q2; r3s += q3;
        }
        for (; j < n; j++) {
            int2 p0 = st[j];
            uint2 h0 = hb[(size_t)p0.x * 32 + lane];
            acc_h4(a0, h0);
            r0s += rel[p0.y * RD + lane];
        }
        e += n;
        __syncwarp();
    }

    float iv = g_inv[v];
    float4 acc;
    acc.x = (a0.x + a1.x + a2.x + a3.x) * iv;
    acc.y = (a0.y + a1.y + a2.y + a3.y) * iv;
    acc.z = (a0.z + a1.z + a2.z + a3.z) * iv;
    acc.w = (a0.w + a1.w + a2.w + a3.w) * iv;
    uint2 outw;
    __half2 lo = __floats2half2_rn(acc.x, acc.y);
    __half2 hi = __floats2half2_rn(acc.z, acc.w);
    outw.x = *reinterpret_cast<unsigned*>(&lo);
    outw.y = *reinterpret_cast<unsigned*>(&hi);
    ((uint2*)g_aggH)[(size_t)v * 32 + lane] = outw;
    g_aggR[v * RD + lane] = __float2half((r0s + r1s + r2s + r3s) * iv);
}

// ---------------- fp16 mma machinery ---------------------------------------------
extern __shared__ float smdyn[];

__device__ __forceinline__ unsigned ldh2(const float* p) {
    float2 f = *(const float2*)p;
    __half2 h = __float22half2_rn(f);
    return *(unsigned*)&h;
}
__device__ __forceinline__ unsigned packh2(float a, float b) {
    __half2 h = __floats2half2_rn(a, b);
    return *(unsigned*)&h;
}

#define MMA_H(CI, A0, A1, A2, A3, B0, B1)                                       \
    asm("mma.sync.aligned.m16n8k16.row.col.f32.f16.f16.f32 "                    \
        "{%0,%1,%2,%3},{%4,%5,%6,%7},{%8,%9},{%0,%1,%2,%3};"                    \
        : "+f"(c[(CI)]), "+f"(c[(CI)+1]), "+f"(c[(CI)+2]), "+f"(c[(CI)+3])      \
        : "r"(A0), "r"(A1), "r"(A2), "r"(A3), "r"(B0), "r"(B1));

#define MMA_ROW16H(BP)                                                          \
    _Pragma("unroll")                                                           \
    for (int nt = 0; nt < 16; nt++) {                                           \
        uint2 b = (BP)[nt * 32];                                                \
        MMA_H(nt * 4, a0, a1, a2, a3, b.x, b.y)                                 \
    }

// ---------------- input projection ------------------------------------------------
__global__ __launch_bounds__(512) void k_input(
    const float* __restrict__ x, const int* __restrict__ label,
    const float* __restrict__ lemb, const float* __restrict__ W,
    const float* __restrict__ b, __half* __restrict__ hout)
{
    float* bs = smdyn;
    uint2* Bp = (uint2*)(bs + DM);           // 10*512 uint2

    int tid = threadIdx.x;
    for (int idx = tid; idx < 10 * 512; idx += 512) {
        int kk = idx >> 9, r = idx & 511;
        int nt = r >> 5, ln = r & 31;
        int n = nt * 8 + (ln >> 2);
        int kb = kk * 16 + (ln & 3) * 2;
        unsigned r0 = packh2(W[kb * DM + n],       W[(kb + 1) * DM + n]);
        unsigned r1 = packh2(W[(kb + 8) * DM + n], W[(kb + 9) * DM + n]);
        Bp[idx] = make_uint2(r0, r1);
    }
    for (int i = tid; i < DM; i += 512) bs[i] = b[i];
    __syncthreads();

    int w = tid >> 5, lane = tid & 31, q = lane & 3, g = lane >> 2;
    const uint2* bpl = Bp + lane;

    for (int tb = blockIdx.x; tb < NT2; tb += gridDim.x) {
        int v0w = tb * 256 + w * 16;
        if (v0w >= NN) continue;
        int va = min(v0w + g, NN - 1);
        int vb = min(v0w + g + 8, NN - 1);
        int la = __ldg(&label[va]);
        int lb = __ldg(&label[vb]);

        float c[64];
        #pragma unroll
        for (int i = 0; i < 64; i++) c[i] = 0.f;

        #pragma unroll
        for (int kk = 0; kk < 8; kk++) {
            int kb = kk * 16 + q * 2;
            unsigned a0 = ldh2(x + (size_t)va * DM + kb);
            unsigned a1 = ldh2(x + (size_t)vb * DM + kb);
            unsigned a2 = ldh2(x + (size_t)va * DM + kb + 8);
            unsigned a3 = ldh2(x + (size_t)vb * DM + kb + 8);
            const uint2* bp = bpl + kk * 512;
            MMA_ROW16H(bp)
        }
        #pragma unroll
        for (int kk = 8; kk < 10; kk++) {
            int kb = kk * 16 + q * 2 - 128;
            unsigned a0 = ldh2(lemb + (size_t)la * RD + kb);
            unsigned a1 = ldh2(lemb + (size_t)lb * RD + kb);
            unsigned a2 = ldh2(lemb + (size_t)la * RD + kb + 8);
            unsigned a3 = ldh2(lemb + (size_t)lb * RD + kb + 8);
            const uint2* bp = bpl + kk * 512;
            MMA_ROW16H(bp)
        }

        int ra = v0w + g, rb = v0w + g + 8;
        #pragma unroll
        for (int nt = 0; nt < 16; nt++) {
            float2 bv = *(float2*)(bs + nt * 8 + 2 * q);
            if (ra < NN) {
                *(unsigned*)(hout + (size_t)ra * DM + nt * 8 + 2 * q) =
                    packh2(fmaxf(c[nt*4+0] + bv.x, 0.f), fmaxf(c[nt*4+1] + bv.y, 0.f));
            }
            if (rb < NN) {
                *(unsigned*)(hout + (size_t)rb * DM + nt * 8 + 2 * q) =
                    packh2(fmaxf(c[nt*4+2] + bv.x, 0.f), fmaxf(c[nt*4+3] + bv.y, 0.f));
            }
        }
    }
}

// ---------------- nodeS: partial = hin @ Wself ------------------------------------
__global__ __launch_bounds__(512) void k_nodeS(
    const __half* __restrict__ hin, const float* __restrict__ Wself)
{
    uint2* Bp = (uint2*)smdyn;               // 8*512 uint2
    int tid = threadIdx.x;
    for (int idx = tid; idx < 8 * 512; idx += 512) {
        int kk = idx >> 9, r = idx & 511;
        int nt = r >> 5, ln = r & 31;
        int n = nt * 8 + (ln >> 2);
        int kb = kk * 16 + (ln & 3) * 2;
        Bp[idx] = make_uint2(packh2(Wself[kb * DM + n],       Wself[(kb + 1) * DM + n]),
                             packh2(Wself[(kb + 8) * DM + n], Wself[(kb + 9) * DM + n]));
    }
    __syncthreads();

    int w = tid >> 5, lane = tid & 31, q = lane & 3, g = lane >> 2;
    const uint2* bpl = Bp + lane;

    for (int tb = blockIdx.x; tb < NT2; tb += gridDim.x) {
        int v0w = tb * 256 + w * 16;
        if (v0w >= NN) continue;
        int va = min(v0w + g, NN - 1);
        int vb = min(v0w + g + 8, NN - 1);

        float c[64];
        #pragma unroll
        for (int i = 0; i < 64; i++) c[i] = 0.f;

        #pragma unroll
        for (int kk = 0; kk < 8; kk++) {
            int kb = kk * 16 + q * 2;
            unsigned a0 = *(const unsigned*)(hin + (size_t)va * DM + kb);
            unsigned a1 = *(const unsigned*)(hin + (size_t)vb * DM + kb);
            unsigned a2 = *(const unsigned*)(hin + (size_t)va * DM + kb + 8);
            unsigned a3 = *(const unsigned*)(hin + (size_t)vb * DM + kb + 8);
            const uint2* bp = bpl + kk * 512;
            MMA_ROW16H(bp)
        }

        int ra = v0w + g, rb = v0w + g + 8;
        #pragma unroll
        for (int nt = 0; nt < 16; nt++) {
            if (ra < NN)
                *(float2*)(g_part + (size_t)ra * DM + nt * 8 + 2 * q) =
                    make_float2(c[nt*4+0], c[nt*4+1]);
            if (rb < NN)
                *(float2*)(g_part + (size_t)rb * DM + nt * 8 + 2 * q) =
                    make_float2(c[nt*4+2], c[nt*4+3]);
        }
    }
}

// ---------------- nodeR: part + aggH@Wn + aggR@Wr + bias + relu + LN --------------
__global__ __launch_bounds__(512) void k_nodeR(
    const float* __restrict__ Wn, const float* __restrict__ Wr,
    const float* __restrict__ bias, const float* __restrict__ lng,
    const float* __restrict__ lnb,
    __half* __restrict__ hout_h, float* __restrict__ hout_f)
{
    float* bs  = smdyn;
    float* gs  = bs + DM;
    float* lbs = gs + DM;
    uint2* Bp  = (uint2*)(lbs + DM);         // 10*512 uint2

    int tid = threadIdx.x;
    for (int idx = tid; idx < 10 * 512; idx += 512) {
        int kk = idx >> 9, r = idx & 511;
        int nt = r >> 5, ln = r & 31;
        int n = nt * 8 + (ln >> 2);
        int kb = kk * 16 + (ln & 3) * 2;
        float w00, w01, w10, w11;
        if (kb < 128) {
            w00 = Wn[kb * DM + n];       w01 = Wn[(kb + 1) * DM + n];
            w10 = Wn[(kb + 8) * DM + n]; w11 = Wn[(kb + 9) * DM + n];
        } else {
            int k2 = kb - 128;
            w00 = Wr[k2 * DM + n];       w01 = Wr[(k2 + 1) * DM + n];
            w10 = Wr[(k2 + 8) * DM + n]; w11 = Wr[(k2 + 9) * DM + n];
        }
        Bp[idx] = make_uint2(packh2(w00, w01), packh2(w10, w11));
    }
    for (int i = tid; i < DM; i += 512) {
        bs[i] = bias[i]; gs[i] = lng[i]; lbs[i] = lnb[i];
    }
    __syncthreads();

    int w = tid >> 5, lane = tid & 31, q = lane & 3, g = lane >> 2;
    const uint2* bpl = Bp + lane;

    for (int tb = blockIdx.x; tb < NT2; tb += gridDim.x) {
        int v0w = tb * 256 + w * 16;
        if (v0w >= NN) continue;
        int va = min(v0w + g, NN - 1);
        int vb = min(v0w + g + 8, NN - 1);

        float c[64];
        #pragma unroll
        for (int nt = 0; nt < 16; nt++) {
            float2 pa = *(const float2*)(g_part + (size_t)va * DM + nt * 8 + 2 * q);
            float2 pb = *(const float2*)(g_part + (size_t)vb * DM + nt * 8 + 2 * q);
            c[nt*4+0] = pa.x; c[nt*4+1] = pa.y;
            c[nt*4+2] = pb.x; c[nt*4+3] = pb.y;
        }

        #pragma unroll
        for (int kk = 0; kk < 8; kk++) {
            int kb = kk * 16 + q * 2;
            unsigned a0 = *(const unsigned*)(g_aggH + (size_t)va * DM + kb);
            unsigned a1 = *(const unsigned*)(g_aggH + (size_t)vb * DM + kb);
            unsigned a2 = *(const unsigned*)(g_aggH + (size_t)va * DM + kb + 8);
            unsigned a3 = *(const unsigned*)(g_aggH + (size_t)vb * DM + kb + 8);
            const uint2* bp = bpl + kk * 512;
            MMA_ROW16H(bp)
        }
        #pragma unroll
        for (int kk = 8; kk < 10; kk++) {
            int kb = (kk - 8) * 16 + q * 2;
            unsigned a0 = *(const unsigned*)(g_aggR + (size_t)va * RD + kb);
            unsigned a1 = *(const unsigned*)(g_aggR + (size_t)vb * RD + kb);
            unsigned a2 = *(const unsigned*)(g_aggR + (size_t)va * RD + kb + 8);
            unsigned a3 = *(const unsigned*)(g_aggR + (size_t)vb * RD + kb + 8);
            const uint2* bp = bpl + kk * 512;
            MMA_ROW16H(bp)
        }

        float s1a = 0.f, s2a = 0.f, s1b = 0.f, s2b = 0.f;
        #pragma unroll
        for (int nt = 0; nt < 16; nt++) {
            float2 bv = *(float2*)(bs + nt * 8 + 2 * q);
            float c0 = fmaxf(c[nt*4+0] + bv.x, 0.f);
            float c1 = fmaxf(c[nt*4+1] + bv.y, 0.f);
            float c2 = fmaxf(c[nt*4+2] + bv.x, 0.f);
            float c3 = fmaxf(c[nt*4+3] + bv.y, 0.f);
            c[nt*4+0] = c0; c[nt*4+1] = c1; c[nt*4+2] = c2; c[nt*4+3] = c3;
            s1a += c0 + c1; s2a += c0 * c0 + c1 * c1;
            s1b += c2 + c3; s2b += c2 * c2 + c3 * c3;
        }
        #pragma unroll
        for (int m = 1; m <= 2; m <<= 1) {
            s1a += __shfl_xor_sync(0xffffffffu, s1a, m);
            s2a += __shfl_xor_sync(0xffffffffu, s2a, m);
            s1b += __shfl_xor_sync(0xffffffffu, s1b, m);
            s2b += __shfl_xor_sync(0xffffffffu, s2b, m);
        }
        float mua = s1a * (1.f / 128.f);
        float rsa = rsqrtf(s2a * (1.f / 128.f) - mua * mua + LN_EPS);
        float mub = s1b * (1.f / 128.f);
        float rsb = rsqrtf(s2b * (1.f / 128.f) - mub * mub + LN_EPS);

        int ra = v0w + g, rb = v0w + g + 8;
        if (hout_f) {
            #pragma unroll
            for (int nt = 0; nt < 16; nt++) {
                float2 gv = *(float2*)(gs + nt * 8 + 2 * q);
                float2 lv = *(float2*)(lbs + nt * 8 + 2 * q);
                if (ra < NN) {
                    float2 o = make_float2((c[nt*4+0] - mua) * rsa * gv.x + lv.x,
                                           (c[nt*4+1] - mua) * rsa * gv.y + lv.y);
                    *(float2*)(hout_f + (size_t)ra * DM + nt * 8 + 2 * q) = o;
                }
                if (rb < NN) {
                    float2 o = make_float2((c[nt*4+2] - mub) * rsb * gv.x + lv.x,
                                           (c[nt*4+3] - mub) * rsb * gv.y + lv.y);
                    *(float2*)(hout_f + (size_t)rb * DM + nt * 8 + 2 * q) = o;
                }
            }
        } else {
            #pragma unroll
            for (int nt = 0; nt < 16; nt++) {
                float2 gv = *(float2*)(gs + nt * 8 + 2 * q);
                float2 lv = *(float2*)(lbs + nt * 8 + 2 * q);
                if (ra < NN) {
                    *(unsigned*)(hout_h + (size_t)ra * DM + nt * 8 + 2 * q) =
                        packh2((c[nt*4+0] - mua) * rsa * gv.x + lv.x,
                               (c[nt*4+1] - mua) * rsa * gv.y + lv.y);
                }
                if (rb < NN) {
                    *(unsigned*)(hout_h + (size_t)rb * DM + nt * 8 + 2 * q) =
                        packh2((c[nt*4+2] - mub) * rsb * gv.x + lv.x,
                               (c[nt*4+3] - mub) * rsb * gv.y + lv.y);
                }
            }
        }
    }
}

// ---------------- host launch ------------------------------------------------------
extern "C" void kernel_launch(void* const* d_in, const int* in_sizes, int n_in,
                              void* d_out, int out_size)
{
    const float* x      = (const float*)d_in[0];
    const int*   label  = (const int*)d_in[1];
    const int*   eidx   = (const int*)d_in[2];
    const int*   erel   = (const int*)d_in[3];
    const float* lemb   = (const float*)d_in[4];
    const float* Win    = (const float*)d_in[5];
    const float* bin    = (const float*)d_in[6];
    const float* relemb = (const float*)d_in[7];
    const float* Wn     = (const float*)d_in[8];
    const float* Wself  = (const float*)d_in[9];
    const float* bself  = (const float*)d_in[10];
    const float* Wr     = (const float*)d_in[11];
    const float* lng    = (const float*)d_in[12];
    const float* lnb    = (const float*)d_in[13];
    float* out = (float*)d_out;

    __half *p_hA, *p_hB;
    int *p_deg;
    cudaGetSymbolAddress((void**)&p_hA,  g_hA);
    cudaGetSymbolAddress((void**)&p_hB,  g_hB);
    cudaGetSymbolAddress((void**)&p_deg, g_deg);

    const int smemI = 512 + 10 * 512 * 8;          // 41472
    const int smemS = 8 * 512 * 8;                 // 32768
    const int smemR = 1536 + 10 * 512 * 8;         // 42496
    cudaFuncSetAttribute(k_input, cudaFuncAttributeMaxDynamicSharedMemorySize, smemI);
    cudaFuncSetAttribute(k_nodeS, cudaFuncAttributeMaxDynamicSharedMemorySize, smemS);
    cudaFuncSetAttribute(k_nodeR, cudaFuncAttributeMaxDynamicSharedMemorySize, smemR);

    cudaStream_t s2;
    cudaEvent_t evFork, evIn, evS0, evN0, evS1;
    cudaStreamCreateWithFlags(&s2, cudaStreamNonBlocking);
    cudaEventCreateWithFlags(&evFork, cudaEventDisableTiming);
    cudaEventCreateWithFlags(&evIn,   cudaEventDisableTiming);
    cudaEventCreateWithFlags(&evS0,   cudaEventDisableTiming);
    cudaEventCreateWithFlags(&evN0,   cudaEventDisableTiming);
    cudaEventCreateWithFlags(&evS1,   cudaEventDisableTiming);

    cudaEventRecord(evFork, 0);
    cudaStreamWaitEvent(s2, evFork, 0);

    // s2: input projection, then self-GEMM of layer 0
    k_input<<<148, 512, smemI, s2>>>(x, label, lemb, Win, bin, p_hA);
    cudaEventRecord(evIn, s2);
    k_nodeS<<<148, 512, smemS, s2>>>(p_hA, Wself + 0 * DM * DM);
    cudaEventRecord(evS0, s2);

    // s0: CSR build (parallel scan), then layer-0 gather
    cudaMemsetAsync(p_deg, 0, NN * sizeof(int));
    k_deg<<<(EE + 255) / 256, 256>>>(eidx + EE);
    k_scanA<<<SCAN_B, 1024>>>();
    k_scanB<<<1, 64>>>();
    k_scanC<<<SCAN_B, 1024>>>();
    k_scatter<<<(EE + 255) / 256, 256>>>(eidx, eidx + EE, erel);
    cudaStreamWaitEvent(0, evIn, 0);
    k_gather<<<(NN + 7) / 8, 256>>>(p_hA, relemb + 0 * 1024 * RD);

    // s0: layer-0 rest
    cudaStreamWaitEvent(0, evS0, 0);
    k_nodeR<<<148, 512, smemR>>>(Wn + 0 * DM * DM, Wr + 0 * RD * DM,
                                 bself + 0 * DM, lng + 0 * DM, lnb + 0 * DM,
                                 p_hB, (float*)nullptr);
    cudaEventRecord(evN0, 0);

    // layer 1: s2 self-GEMM || s0 gather
    cudaStreamWaitEvent(s2, evN0, 0);
    k_nodeS<<<148, 512, smemS, s2>>>(p_hB, Wself + 1 * DM * DM);
    cudaEventRecord(evS1, s2);

    k_gather<<<(NN + 7) / 8, 256>>>(p_hB, relemb + 1 * 1024 * RD);
    cudaStreamWaitEvent(0, evS1, 0);
    k_nodeR<<<148, 512, smemR>>>(Wn + 1 * DM * DM, Wr + 1 * RD * DM,
                                 bself + 1 * DM, lng + 1 * DM, lnb + 1 * DM,
                                 (__half*)nullptr, out);

    cudaEventDestroy(evFork);
    cudaEventDestroy(evIn);
    cudaEventDestroy(evS0);
    cudaEventDestroy(evN0);
    cudaEventDestroy(evS1);
    cudaStreamDestroy(s2);
}